// round 14
// baseline (speedup 1.0000x reference)
#include <cuda_runtime.h>
#include <stdint.h>

#define BN      16384
#define IN_DIM  256
#define HID     128
#define NCLS    8
#define T_STEPS 64
#define BETA    0.9f
#define NSM     148
#define NB3     222            // k3 sample blocks per class-half (3 CTAs/SM)

// Scratch (no cudaMalloc allowed)
__device__ float g_cur1[BN * HID];          // 8 MB
__device__ uint4 g_masks[T_STEPS * BN];     // 16 MB  [t][s] spike masks
__device__ float g_W1T[IN_DIM * HID];       // 128 KB W1 transposed: [k][h]

// packed fp32x2 helpers — per-32-bit-lane IEEE ops, lanes independent
static __device__ __forceinline__ void ffma2(unsigned long long& d,
                                             unsigned long long a,
                                             unsigned long long b)
{
    asm("fma.rn.f32x2 %0, %1, %2, %0;" : "+l"(d) : "l"(a), "l"(b));
}

static __device__ __forceinline__ unsigned long long fdup(float v)
{
    unsigned long long r;
    unsigned u = __float_as_uint(v);
    asm("mov.b64 %0, {%1, %1};" : "=l"(r) : "r"(u));
    return r;
}

static __device__ __forceinline__ unsigned long long fpack(float lo, float hi)
{
    unsigned long long r;
    asm("mov.b64 %0, {%1, %2};" : "=l"(r) : "f"(lo), "f"(hi));
    return r;
}

static __device__ __forceinline__ void funpack(unsigned long long v,
                                               float& lo, float& hi)
{
    asm("mov.b64 {%0, %1}, %2;" : "=f"(lo), "=f"(hi) : "l"(v));
}

// ---------------------------------------------------------------------------
// K0: W1T[k][h] = W1[h][k] — tiled transpose, coalesced both sides.
// ---------------------------------------------------------------------------
__global__ void k0_w1t(const float* __restrict__ W1)
{
    __shared__ float t[32][33];
    const int kb = blockIdx.x * 32;
    const int hb = blockIdx.y * 32;
    const int lx = threadIdx.x;
    const int ly = threadIdx.y;
#pragma unroll
    for (int i = 0; i < 4; i++)
        t[ly + i * 8][lx] = W1[(hb + ly + i * 8) * IN_DIM + kb + lx];
    __syncthreads();
#pragma unroll
    for (int i = 0; i < 4; i++)
        g_W1T[(kb + ly + i * 8) * HID + hb + lx] = t[lx][ly + i * 8];
}

// ---------------------------------------------------------------------------
// K1: cur1 = x @ W1^T + b1. (R13 version, bitwise-stable k-ascending chains.)
// ---------------------------------------------------------------------------
#define XS_STRIDE 36
#define XS_BYTES  (64 * XS_STRIDE * 4)
#define WS_BYTES  (32 * HID * 4)
#define K1_SMEM   (2 * (XS_BYTES + WS_BYTES))

__global__ __launch_bounds__(128) void k1_fc1(const float* __restrict__ x,
                                              const float* __restrict__ b1)
{
    extern __shared__ char dsm[];
    float* xsb[2] = {(float*)dsm, (float*)(dsm + XS_BYTES)};
    float* wsb[2] = {(float*)(dsm + 2 * XS_BYTES),
                     (float*)(dsm + 2 * XS_BYTES + WS_BYTES)};

    const int tid = threadIdx.x;
    const int bs  = blockIdx.x * 64;
    const int c   = tid & 7;
    const int r   = tid >> 3;

    int xfs[4], xfk[4];
#pragma unroll
    for (int i = 0; i < 4; i++) {
        int f = i * 128 + tid;
        xfs[i] = f >> 3;
        xfk[i] = (f & 7) * 4;
    }

    float4 px[4], pw[8];
#pragma unroll
    for (int i = 0; i < 4; i++)
        px[i] = *(const float4*)&x[(bs + xfs[i]) * IN_DIM + xfk[i]];
#pragma unroll
    for (int i = 0; i < 8; i++) {
        int f  = i * 128 + tid;
        int kk = f >> 5;
        int h4 = (f & 31) * 4;
        pw[i] = *(const float4*)&g_W1T[kk * HID + h4];
    }

    unsigned long long acc2[4][8];
#pragma unroll
    for (int p = 0; p < 4; p++)
#pragma unroll
        for (int j = 0; j < 8; j++) acc2[p][j] = 0ull;

    for (int ch = 0; ch < IN_DIM / 32; ch++) {
        float* xs = xsb[ch & 1];
        float* ws = wsb[ch & 1];
#pragma unroll
        for (int i = 0; i < 4; i++)
            *(float4*)&xs[xfs[i] * XS_STRIDE + xfk[i]] = px[i];
#pragma unroll
        for (int i = 0; i < 8; i++) {
            int f  = i * 128 + tid;
            int kk = f >> 5;
            int h4 = (f & 31) * 4;
            *(float4*)&ws[kk * HID + h4] = pw[i];
        }
        __syncthreads();

        if (ch + 1 < IN_DIM / 32) {
            int kc = (ch + 1) * 32;
#pragma unroll
            for (int i = 0; i < 4; i++)
                px[i] = *(const float4*)&x[(bs + xfs[i]) * IN_DIM + kc + xfk[i]];
#pragma unroll
            for (int i = 0; i < 8; i++) {
                int f  = i * 128 + tid;
                int kk = f >> 5;
                int h4 = (f & 31) * 4;
                pw[i] = *(const float4*)&g_W1T[(kc + kk) * HID + h4];
            }
        }

#pragma unroll
        for (int k = 0; k < 32; k += 4) {
            float4 xv[8];
#pragma unroll
            for (int j = 0; j < 8; j++)
                xv[j] = *(const float4*)&xs[(c + 8 * j) * XS_STRIDE + k];
            ulonglong2 wa[4], wb[4];
#pragma unroll
            for (int kk = 0; kk < 4; kk++) {
                wa[kk] = *(const ulonglong2*)&ws[(k + kk) * HID + r * 8];
                wb[kk] = *(const ulonglong2*)&ws[(k + kk) * HID + r * 8 + 4];
            }
#pragma unroll
            for (int kk = 0; kk < 4; kk++) {
#pragma unroll
                for (int j = 0; j < 8; j++) {
                    float xf = (kk == 0) ? xv[j].x : (kk == 1) ? xv[j].y
                             : (kk == 2) ? xv[j].z : xv[j].w;
                    unsigned long long xx = fdup(xf);
                    ffma2(acc2[0][j], xx, wa[kk].x);
                    ffma2(acc2[1][j], xx, wa[kk].y);
                    ffma2(acc2[2][j], xx, wb[kk].x);
                    ffma2(acc2[3][j], xx, wb[kk].y);
                }
            }
        }
    }

    float4 b1v0 = *(const float4*)&b1[r * 8];
    float4 b1v1 = *(const float4*)&b1[r * 8 + 4];
#pragma unroll
    for (int j = 0; j < 8; j++) {
        int s = bs + c + 8 * j;
        float4 o0, o1;
        o0.x = __uint_as_float((unsigned)(acc2[0][j] & 0xffffffffull)) + b1v0.x;
        o0.y = __uint_as_float((unsigned)(acc2[0][j] >> 32))           + b1v0.y;
        o0.z = __uint_as_float((unsigned)(acc2[1][j] & 0xffffffffull)) + b1v0.z;
        o0.w = __uint_as_float((unsigned)(acc2[1][j] >> 32))           + b1v0.w;
        o1.x = __uint_as_float((unsigned)(acc2[2][j] & 0xffffffffull)) + b1v1.x;
        o1.y = __uint_as_float((unsigned)(acc2[2][j] >> 32))           + b1v1.y;
        o1.z = __uint_as_float((unsigned)(acc2[3][j] & 0xffffffffull)) + b1v1.z;
        o1.w = __uint_as_float((unsigned)(acc2[3][j] >> 32))           + b1v1.w;
        *(float4*)&g_cur1[s * HID + r * 8]     = o0;
        *(float4*)&g_cur1[s * HID + r * 8 + 4] = o1;
    }
}

// ---------------------------------------------------------------------------
// K2: layer-1 LIF + ballots, sample pairs packed in f32x2 (bitwise identical:
// per-lane fma.rn / add.rn; m - rf == m + (-rf) exactly for rf in {0,1,0.0}).
// Warp = 32 hid x 4 samples. Block = 256 thr = 8 samples.
// ---------------------------------------------------------------------------
__global__ __launch_bounds__(256) void k2_lif1()
{
    __shared__ uint32_t sm[T_STEPS][8][4];

    const int tid  = threadIdx.x;
    const int w    = tid >> 5;
    const int lane = tid & 31;
    const int g    = w & 3;
    const int q    = w >> 2;
    const int sb   = blockIdx.x * 8 + q * 4;
    const int h    = g * 32 + lane;

    float c0 = g_cur1[(sb + 0) * HID + h];
    float c1 = g_cur1[(sb + 1) * HID + h];
    float c2 = g_cur1[(sb + 2) * HID + h];
    float c3 = g_cur1[(sb + 3) * HID + h];

    const unsigned long long beta2 = fdup(BETA);
    unsigned long long cur01 = fpack(c0, c1);
    unsigned long long cur23 = fpack(c2, c3);
    unsigned long long mem01 = fpack(0.0f, 0.0f);
    unsigned long long mem23 = fpack(0.0f, 0.0f);
    unsigned long long rst01 = fpack(-0.0f, -0.0f);
    unsigned long long rst23 = fpack(-0.0f, -0.0f);

    const unsigned FULL = 0xffffffffu;

#pragma unroll 4
    for (int t = 0; t < T_STEPS; t++) {
        // m = beta*m + cur  (per-lane fma.rn), then m += -rst (per-lane add.rn)
        asm("fma.rn.f32x2 %0, %1, %0, %2;" : "+l"(mem01) : "l"(beta2), "l"(cur01));
        asm("fma.rn.f32x2 %0, %1, %0, %2;" : "+l"(mem23) : "l"(beta2), "l"(cur23));
        asm("add.rn.f32x2 %0, %0, %1;" : "+l"(mem01) : "l"(rst01));
        asm("add.rn.f32x2 %0, %0, %1;" : "+l"(mem23) : "l"(rst23));

        float m0, m1, m2, m3;
        funpack(mem01, m0, m1);
        funpack(mem23, m2, m3);

        unsigned b0 = __ballot_sync(FULL, m0 > 1.0f);
        unsigned b1 = __ballot_sync(FULL, m1 > 1.0f);
        unsigned b2 = __ballot_sync(FULL, m2 > 1.0f);
        unsigned b3 = __ballot_sync(FULL, m3 > 1.0f);

        float r0 = (m0 > 1.0f) ? -1.0f : -0.0f;
        float r1 = (m1 > 1.0f) ? -1.0f : -0.0f;
        float r2 = (m2 > 1.0f) ? -1.0f : -0.0f;
        float r3 = (m3 > 1.0f) ? -1.0f : -0.0f;
        rst01 = fpack(r0, r1);
        rst23 = fpack(r2, r3);

        if (lane == 0) {
            sm[t][q * 4 + 0][g] = b0;
            sm[t][q * 4 + 1][g] = b1;
            sm[t][q * 4 + 2][g] = b2;
            sm[t][q * 4 + 3][g] = b3;
        }
    }
    __syncthreads();

    for (int idx = tid; idx < T_STEPS * 8; idx += 256) {
        int t  = idx >> 3;
        int sl = idx & 7;
        g_masks[t * BN + blockIdx.x * 8 + sl] = *(const uint4*)&sm[t][sl][0];
    }
}

// ---------------------------------------------------------------------------
// K3: fused layer-2 LUT + LIF (trees bitwise == R9), depth-2 pipeline.
// Grid 222 blocks x 2 halves = 444 CTAs = 3/SM (12 warps/SM for latency
// hiding); block bi covers samples [bi*BN/222, (bi+1)*BN/222) (73-74).
// ---------------------------------------------------------------------------
static __device__ __forceinline__ float4 f4add(float4 a, float4 b)
{
    return make_float4(a.x + b.x, a.y + b.y, a.z + b.z, a.w + b.w);
}

static __device__ __forceinline__ float4 lut_tree(const float* __restrict__ lut,
                                                  uint4 m, float4 b2v)
{
    uint32_t w[4] = {m.x, m.y, m.z, m.w};
    float4 sg[4];
#pragma unroll
    for (int g = 0; g < 4; g++) {
        const float* lg = &lut[g * 4096];
        uint32_t wg = w[g];
        float4 q0 = *(const float4*)&lg[            ((wg        & 255u) << 2)];
        float4 q1 = *(const float4*)&lg[1 * 1024 + (((wg >> 8)  & 255u) << 2)];
        float4 q2 = *(const float4*)&lg[2 * 1024 + (((wg >> 16) & 255u) << 2)];
        float4 q3 = *(const float4*)&lg[3 * 1024 + ((wg >> 24)          << 2)];
        sg[g] = f4add(f4add(q0, q1), f4add(q2, q3));
    }
    return f4add(f4add(f4add(sg[0], sg[1]), f4add(sg[2], sg[3])), b2v);
}

__global__ __launch_bounds__(128) void k3_lif2(const float* __restrict__ W2,
                                               const float* __restrict__ b2,
                                               float* __restrict__ out)
{
    extern __shared__ float lut[];   // [16][256] float4
    const int tid  = threadIdx.x;
    const int half = blockIdx.x & 1;
    const int bi   = blockIdx.x >> 1;          // 0..221

    {
        const int chunk = tid >> 3;            // 0..15
        const int bbase = (tid & 7) * 32;
        float w[4][8];
#pragma unroll
        for (int cc = 0; cc < 4; cc++)
#pragma unroll
            for (int j = 0; j < 8; j++)
                w[cc][j] = W2[(half * 4 + cc) * HID + chunk * 8 + j];

        for (int i = 0; i < 32; i++) {
            int byt = bbase + i;
            float4 v = make_float4(0.f, 0.f, 0.f, 0.f);
#pragma unroll
            for (int j = 0; j < 8; j++) {
                if ((byt >> j) & 1) {
                    v.x += w[0][j]; v.y += w[1][j];
                    v.z += w[2][j]; v.w += w[3][j];
                }
            }
            *(float4*)&lut[(chunk * 256 + byt) * 4] = v;
        }
    }
    __syncthreads();

    const int s_begin = (bi * BN) / NB3;
    const int s_end   = ((bi + 1) * BN) / NB3;
    const int s       = s_begin + tid;
    if (s >= s_end) return;

    float4 b2v = make_float4(b2[half * 4 + 0], b2[half * 4 + 1],
                             b2[half * 4 + 2], b2[half * 4 + 3]);

    const uint4* mp = &g_masks[s];

    uint4 mc = mp[2 * BN];                    // mask t = 2
    float4 cur = lut_tree(lut, mp[0],  b2v);  // current t = 0
    float4 nxt = lut_tree(lut, mp[BN], b2v);  // current t = 1

    float4 mem = make_float4(0.f, 0.f, 0.f, 0.f);
    float4 acc = mem, rst = mem;

#pragma unroll 2
    for (int t = 0; t < T_STEPS - 2; t++) {
        int tp = (t + 3 < T_STEPS) ? (t + 3) : (T_STEPS - 1);
        uint4 mnew = mp[(size_t)tp * BN];

        float4 n2 = lut_tree(lut, mc, b2v);
        mc = mnew;

        mem.x = fmaf(BETA, mem.x, cur.x) - rst.x;
        mem.y = fmaf(BETA, mem.y, cur.y) - rst.y;
        mem.z = fmaf(BETA, mem.z, cur.z) - rst.z;
        mem.w = fmaf(BETA, mem.w, cur.w) - rst.w;
        rst.x = (mem.x > 1.0f) ? 1.0f : 0.0f;
        rst.y = (mem.y > 1.0f) ? 1.0f : 0.0f;
        rst.z = (mem.z > 1.0f) ? 1.0f : 0.0f;
        rst.w = (mem.w > 1.0f) ? 1.0f : 0.0f;
        acc.x += rst.x; acc.y += rst.y; acc.z += rst.z; acc.w += rst.w;

        cur = nxt;
        nxt = n2;
    }

    // t = 62
    mem.x = fmaf(BETA, mem.x, cur.x) - rst.x;
    mem.y = fmaf(BETA, mem.y, cur.y) - rst.y;
    mem.z = fmaf(BETA, mem.z, cur.z) - rst.z;
    mem.w = fmaf(BETA, mem.w, cur.w) - rst.w;
    rst.x = (mem.x > 1.0f) ? 1.0f : 0.0f;
    rst.y = (mem.y > 1.0f) ? 1.0f : 0.0f;
    rst.z = (mem.z > 1.0f) ? 1.0f : 0.0f;
    rst.w = (mem.w > 1.0f) ? 1.0f : 0.0f;
    acc.x += rst.x; acc.y += rst.y; acc.z += rst.z; acc.w += rst.w;
    cur = nxt;

    // t = 63
    mem.x = fmaf(BETA, mem.x, cur.x) - rst.x;
    mem.y = fmaf(BETA, mem.y, cur.y) - rst.y;
    mem.z = fmaf(BETA, mem.z, cur.z) - rst.z;
    mem.w = fmaf(BETA, mem.w, cur.w) - rst.w;
    acc.x += (mem.x > 1.0f) ? 1.0f : 0.0f;
    acc.y += (mem.y > 1.0f) ? 1.0f : 0.0f;
    acc.z += (mem.z > 1.0f) ? 1.0f : 0.0f;
    acc.w += (mem.w > 1.0f) ? 1.0f : 0.0f;

    *(float4*)&out[s * 8 + half * 4] = acc;
}

// ---------------------------------------------------------------------------
extern "C" void kernel_launch(void* const* d_in, const int* in_sizes, int n_in,
                              void* d_out, int out_size)
{
    const float* x  = (const float*)d_in[0];
    const float* W1 = (const float*)d_in[1];
    const float* b1 = (const float*)d_in[2];
    const float* W2 = (const float*)d_in[3];
    const float* b2 = (const float*)d_in[4];
    float* out = (float*)d_out;

    k0_w1t<<<dim3(8, 4), dim3(32, 8)>>>(W1);

    cudaFuncSetAttribute(k1_fc1, cudaFuncAttributeMaxDynamicSharedMemorySize, K1_SMEM);
    k1_fc1<<<BN / 64, 128, K1_SMEM>>>(x, b1);

    k2_lif1<<<BN / 8, 256>>>();

    cudaFuncSetAttribute(k3_lif2, cudaFuncAttributeMaxDynamicSharedMemorySize, 65536);
    k3_lif2<<<NB3 * 2, 128, 65536>>>(W2, b2, out);
}

// round 15
// speedup vs baseline: 1.0435x; 1.0435x over previous
#include <cuda_runtime.h>
#include <stdint.h>

#define BN      16384
#define IN_DIM  256
#define HID     128
#define NCLS    8
#define T_STEPS 64
#define BETA    0.9f
#define NSM     148

// Scratch (no cudaMalloc allowed)
__device__ float g_cur1[BN * HID];          // 8 MB
__device__ uint4 g_masks[T_STEPS * BN];     // 16 MB  [t][s] spike masks
__device__ float g_W1T[IN_DIM * HID];       // 128 KB W1 transposed: [k][h]

// packed fp32x2 helpers — per-32-bit-lane IEEE ops, lanes independent
static __device__ __forceinline__ void ffma2(unsigned long long& d,
                                             unsigned long long a,
                                             unsigned long long b)
{
    asm("fma.rn.f32x2 %0, %1, %2, %0;" : "+l"(d) : "l"(a), "l"(b));
}

static __device__ __forceinline__ unsigned long long fdup(float v)
{
    unsigned long long r;
    unsigned u = __float_as_uint(v);
    asm("mov.b64 %0, {%1, %1};" : "=l"(r) : "r"(u));
    return r;
}

static __device__ __forceinline__ unsigned long long fpack(float lo, float hi)
{
    unsigned long long r;
    asm("mov.b64 %0, {%1, %2};" : "=l"(r) : "f"(lo), "f"(hi));
    return r;
}

static __device__ __forceinline__ void funpack(unsigned long long v,
                                               float& lo, float& hi)
{
    asm("mov.b64 {%0, %1}, %2;" : "=f"(lo), "=f"(hi) : "l"(v));
}

// ---------------------------------------------------------------------------
// K0: W1T[k][h] = W1[h][k] — tiled transpose, coalesced both sides.
// ---------------------------------------------------------------------------
__global__ void k0_w1t(const float* __restrict__ W1)
{
    __shared__ float t[32][33];
    const int kb = blockIdx.x * 32;
    const int hb = blockIdx.y * 32;
    const int lx = threadIdx.x;
    const int ly = threadIdx.y;
#pragma unroll
    for (int i = 0; i < 4; i++)
        t[ly + i * 8][lx] = W1[(hb + ly + i * 8) * IN_DIM + kb + lx];
    __syncthreads();
#pragma unroll
    for (int i = 0; i < 4; i++)
        g_W1T[(kb + ly + i * 8) * HID + hb + lx] = t[lx][ly + i * 8];
}

// ---------------------------------------------------------------------------
// K1: cur1 = x @ W1^T + b1. (R13/R14 version, bitwise-stable k-ascending.)
// ---------------------------------------------------------------------------
#define XS_STRIDE 36
#define XS_BYTES  (64 * XS_STRIDE * 4)
#define WS_BYTES  (32 * HID * 4)
#define K1_SMEM   (2 * (XS_BYTES + WS_BYTES))

__global__ __launch_bounds__(128) void k1_fc1(const float* __restrict__ x,
                                              const float* __restrict__ b1)
{
    extern __shared__ char dsm[];
    float* xsb[2] = {(float*)dsm, (float*)(dsm + XS_BYTES)};
    float* wsb[2] = {(float*)(dsm + 2 * XS_BYTES),
                     (float*)(dsm + 2 * XS_BYTES + WS_BYTES)};

    const int tid = threadIdx.x;
    const int bs  = blockIdx.x * 64;
    const int c   = tid & 7;
    const int r   = tid >> 3;

    int xfs[4], xfk[4];
#pragma unroll
    for (int i = 0; i < 4; i++) {
        int f = i * 128 + tid;
        xfs[i] = f >> 3;
        xfk[i] = (f & 7) * 4;
    }

    float4 px[4], pw[8];
#pragma unroll
    for (int i = 0; i < 4; i++)
        px[i] = *(const float4*)&x[(bs + xfs[i]) * IN_DIM + xfk[i]];
#pragma unroll
    for (int i = 0; i < 8; i++) {
        int f  = i * 128 + tid;
        int kk = f >> 5;
        int h4 = (f & 31) * 4;
        pw[i] = *(const float4*)&g_W1T[kk * HID + h4];
    }

    unsigned long long acc2[4][8];
#pragma unroll
    for (int p = 0; p < 4; p++)
#pragma unroll
        for (int j = 0; j < 8; j++) acc2[p][j] = 0ull;

    for (int ch = 0; ch < IN_DIM / 32; ch++) {
        float* xs = xsb[ch & 1];
        float* ws = wsb[ch & 1];
#pragma unroll
        for (int i = 0; i < 4; i++)
            *(float4*)&xs[xfs[i] * XS_STRIDE + xfk[i]] = px[i];
#pragma unroll
        for (int i = 0; i < 8; i++) {
            int f  = i * 128 + tid;
            int kk = f >> 5;
            int h4 = (f & 31) * 4;
            *(float4*)&ws[kk * HID + h4] = pw[i];
        }
        __syncthreads();

        if (ch + 1 < IN_DIM / 32) {
            int kc = (ch + 1) * 32;
#pragma unroll
            for (int i = 0; i < 4; i++)
                px[i] = *(const float4*)&x[(bs + xfs[i]) * IN_DIM + kc + xfk[i]];
#pragma unroll
            for (int i = 0; i < 8; i++) {
                int f  = i * 128 + tid;
                int kk = f >> 5;
                int h4 = (f & 31) * 4;
                pw[i] = *(const float4*)&g_W1T[(kc + kk) * HID + h4];
            }
        }

#pragma unroll
        for (int k = 0; k < 32; k += 4) {
            float4 xv[8];
#pragma unroll
            for (int j = 0; j < 8; j++)
                xv[j] = *(const float4*)&xs[(c + 8 * j) * XS_STRIDE + k];
            ulonglong2 wa[4], wb[4];
#pragma unroll
            for (int kk = 0; kk < 4; kk++) {
                wa[kk] = *(const ulonglong2*)&ws[(k + kk) * HID + r * 8];
                wb[kk] = *(const ulonglong2*)&ws[(k + kk) * HID + r * 8 + 4];
            }
#pragma unroll
            for (int kk = 0; kk < 4; kk++) {
#pragma unroll
                for (int j = 0; j < 8; j++) {
                    float xf = (kk == 0) ? xv[j].x : (kk == 1) ? xv[j].y
                             : (kk == 2) ? xv[j].z : xv[j].w;
                    unsigned long long xx = fdup(xf);
                    ffma2(acc2[0][j], xx, wa[kk].x);
                    ffma2(acc2[1][j], xx, wa[kk].y);
                    ffma2(acc2[2][j], xx, wb[kk].x);
                    ffma2(acc2[3][j], xx, wb[kk].y);
                }
            }
        }
    }

    float4 b1v0 = *(const float4*)&b1[r * 8];
    float4 b1v1 = *(const float4*)&b1[r * 8 + 4];
#pragma unroll
    for (int j = 0; j < 8; j++) {
        int s = bs + c + 8 * j;
        float4 o0, o1;
        o0.x = __uint_as_float((unsigned)(acc2[0][j] & 0xffffffffull)) + b1v0.x;
        o0.y = __uint_as_float((unsigned)(acc2[0][j] >> 32))           + b1v0.y;
        o0.z = __uint_as_float((unsigned)(acc2[1][j] & 0xffffffffull)) + b1v0.z;
        o0.w = __uint_as_float((unsigned)(acc2[1][j] >> 32))           + b1v0.w;
        o1.x = __uint_as_float((unsigned)(acc2[2][j] & 0xffffffffull)) + b1v1.x;
        o1.y = __uint_as_float((unsigned)(acc2[2][j] >> 32))           + b1v1.y;
        o1.z = __uint_as_float((unsigned)(acc2[3][j] & 0xffffffffull)) + b1v1.z;
        o1.w = __uint_as_float((unsigned)(acc2[3][j] >> 32))           + b1v1.w;
        *(float4*)&g_cur1[s * HID + r * 8]     = o0;
        *(float4*)&g_cur1[s * HID + r * 8 + 4] = o1;
    }
}

// ---------------------------------------------------------------------------
// K2: layer-1 LIF + ballots, sample pairs in f32x2 (R14 version, bitwise
// identical per lane; measured -2.3 us vs scalar).
// ---------------------------------------------------------------------------
__global__ __launch_bounds__(256) void k2_lif1()
{
    __shared__ uint32_t sm[T_STEPS][8][4];

    const int tid  = threadIdx.x;
    const int w    = tid >> 5;
    const int lane = tid & 31;
    const int g    = w & 3;
    const int q    = w >> 2;
    const int sb   = blockIdx.x * 8 + q * 4;
    const int h    = g * 32 + lane;

    float c0 = g_cur1[(sb + 0) * HID + h];
    float c1 = g_cur1[(sb + 1) * HID + h];
    float c2 = g_cur1[(sb + 2) * HID + h];
    float c3 = g_cur1[(sb + 3) * HID + h];

    const unsigned long long beta2 = fdup(BETA);
    unsigned long long cur01 = fpack(c0, c1);
    unsigned long long cur23 = fpack(c2, c3);
    unsigned long long mem01 = fpack(0.0f, 0.0f);
    unsigned long long mem23 = fpack(0.0f, 0.0f);
    unsigned long long rst01 = fpack(-0.0f, -0.0f);
    unsigned long long rst23 = fpack(-0.0f, -0.0f);

    const unsigned FULL = 0xffffffffu;

#pragma unroll 4
    for (int t = 0; t < T_STEPS; t++) {
        asm("fma.rn.f32x2 %0, %1, %0, %2;" : "+l"(mem01) : "l"(beta2), "l"(cur01));
        asm("fma.rn.f32x2 %0, %1, %0, %2;" : "+l"(mem23) : "l"(beta2), "l"(cur23));
        asm("add.rn.f32x2 %0, %0, %1;" : "+l"(mem01) : "l"(rst01));
        asm("add.rn.f32x2 %0, %0, %1;" : "+l"(mem23) : "l"(rst23));

        float m0, m1, m2, m3;
        funpack(mem01, m0, m1);
        funpack(mem23, m2, m3);

        unsigned b0 = __ballot_sync(FULL, m0 > 1.0f);
        unsigned b1 = __ballot_sync(FULL, m1 > 1.0f);
        unsigned b2 = __ballot_sync(FULL, m2 > 1.0f);
        unsigned b3 = __ballot_sync(FULL, m3 > 1.0f);

        float r0 = (m0 > 1.0f) ? -1.0f : -0.0f;
        float r1 = (m1 > 1.0f) ? -1.0f : -0.0f;
        float r2 = (m2 > 1.0f) ? -1.0f : -0.0f;
        float r3 = (m3 > 1.0f) ? -1.0f : -0.0f;
        rst01 = fpack(r0, r1);
        rst23 = fpack(r2, r3);

        if (lane == 0) {
            sm[t][q * 4 + 0][g] = b0;
            sm[t][q * 4 + 1][g] = b1;
            sm[t][q * 4 + 2][g] = b2;
            sm[t][q * 4 + 3][g] = b3;
        }
    }
    __syncthreads();

    for (int idx = tid; idx < T_STEPS * 8; idx += 256) {
        int t  = idx >> 3;
        int sl = idx & 7;
        g_masks[t * BN + blockIdx.x * 8 + sl] = *(const uint4*)&sm[t][sl][0];
    }
}

// ---------------------------------------------------------------------------
// K3: fused layer-2 LUT + LIF (per-unit math bitwise == R13), restructured:
//  - 256 threads/CTA, grid 296 (2 CTAs/SM, single wave — proven config).
//    CTA units (~111 samples) split ~14 per warp -> 16 warp-streams/SM of
//    ~14 active lanes (was 8 streams), same crossbar bytes.
//  - PDL: LUT build (depends only on W2) overlaps k2 via
//    cudaGridDependencySynchronize before mask reads.
// ---------------------------------------------------------------------------
static __device__ __forceinline__ float4 f4add(float4 a, float4 b)
{
    return make_float4(a.x + b.x, a.y + b.y, a.z + b.z, a.w + b.w);
}

static __device__ __forceinline__ float4 lut_tree(const float* __restrict__ lut,
                                                  uint4 m, float4 b2v)
{
    uint32_t w[4] = {m.x, m.y, m.z, m.w};
    float4 sg[4];
#pragma unroll
    for (int g = 0; g < 4; g++) {
        const float* lg = &lut[g * 4096];
        uint32_t wg = w[g];
        float4 q0 = *(const float4*)&lg[            ((wg        & 255u) << 2)];
        float4 q1 = *(const float4*)&lg[1 * 1024 + (((wg >> 8)  & 255u) << 2)];
        float4 q2 = *(const float4*)&lg[2 * 1024 + (((wg >> 16) & 255u) << 2)];
        float4 q3 = *(const float4*)&lg[3 * 1024 + ((wg >> 24)          << 2)];
        sg[g] = f4add(f4add(q0, q1), f4add(q2, q3));
    }
    return f4add(f4add(f4add(sg[0], sg[1]), f4add(sg[2], sg[3])), b2v);
}

__global__ __launch_bounds__(256) void k3_lif2(const float* __restrict__ W2,
                                               const float* __restrict__ b2,
                                               float* __restrict__ out)
{
    extern __shared__ float lut[];   // [16][256] float4 = 64 KB
    const int tid  = threadIdx.x;
    const int half = blockIdx.x & 1;
    const int bi   = blockIdx.x >> 1;          // 0..147

    // LUT build: 256 threads, 16 entries each (values identical to R13).
    {
        const int chunk = tid >> 4;            // 0..15
        const int bbase = (tid & 15) * 16;
        float w[4][8];
#pragma unroll
        for (int cc = 0; cc < 4; cc++)
#pragma unroll
            for (int j = 0; j < 8; j++)
                w[cc][j] = W2[(half * 4 + cc) * HID + chunk * 8 + j];

        for (int i = 0; i < 16; i++) {
            int byt = bbase + i;
            float4 v = make_float4(0.f, 0.f, 0.f, 0.f);
#pragma unroll
            for (int j = 0; j < 8; j++) {
                if ((byt >> j) & 1) {
                    v.x += w[0][j]; v.y += w[1][j];
                    v.z += w[2][j]; v.w += w[3][j];
                }
            }
            *(float4*)&lut[(chunk * 256 + byt) * 4] = v;
        }
    }
    __syncthreads();

#if __CUDA_ARCH__ >= 900
    // PDL join: masks from k2 become visible past this point.
    cudaGridDependencySynchronize();
#endif

    const int s_begin = (bi * BN) / NSM;
    const int s_end   = ((bi + 1) * BN) / NSM;
    const int cnt     = s_end - s_begin;       // 110 or 111
    const int w       = tid >> 5;
    const int lane    = tid & 31;
    const int wcnt    = (cnt + 7) >> 3;        // units per warp (14)
    const int u       = w * wcnt + lane;
    if (lane >= wcnt || u >= cnt) return;
    const int s = s_begin + u;

    float4 b2v = make_float4(b2[half * 4 + 0], b2[half * 4 + 1],
                             b2[half * 4 + 2], b2[half * 4 + 3]);

    const uint4* mp = &g_masks[s];

    uint4 mc = mp[2 * BN];                    // mask t = 2
    float4 cur = lut_tree(lut, mp[0],  b2v);  // current t = 0
    float4 nxt = lut_tree(lut, mp[BN], b2v);  // current t = 1

    float4 mem = make_float4(0.f, 0.f, 0.f, 0.f);
    float4 acc = mem, rst = mem;

#pragma unroll 2
    for (int t = 0; t < T_STEPS - 2; t++) {
        int tp = (t + 3 < T_STEPS) ? (t + 3) : (T_STEPS - 1);
        uint4 mnew = mp[(size_t)tp * BN];

        float4 n2 = lut_tree(lut, mc, b2v);
        mc = mnew;

        mem.x = fmaf(BETA, mem.x, cur.x) - rst.x;
        mem.y = fmaf(BETA, mem.y, cur.y) - rst.y;
        mem.z = fmaf(BETA, mem.z, cur.z) - rst.z;
        mem.w = fmaf(BETA, mem.w, cur.w) - rst.w;
        rst.x = (mem.x > 1.0f) ? 1.0f : 0.0f;
        rst.y = (mem.y > 1.0f) ? 1.0f : 0.0f;
        rst.z = (mem.z > 1.0f) ? 1.0f : 0.0f;
        rst.w = (mem.w > 1.0f) ? 1.0f : 0.0f;
        acc.x += rst.x; acc.y += rst.y; acc.z += rst.z; acc.w += rst.w;

        cur = nxt;
        nxt = n2;
    }

    // t = 62
    mem.x = fmaf(BETA, mem.x, cur.x) - rst.x;
    mem.y = fmaf(BETA, mem.y, cur.y) - rst.y;
    mem.z = fmaf(BETA, mem.z, cur.z) - rst.z;
    mem.w = fmaf(BETA, mem.w, cur.w) - rst.w;
    rst.x = (mem.x > 1.0f) ? 1.0f : 0.0f;
    rst.y = (mem.y > 1.0f) ? 1.0f : 0.0f;
    rst.z = (mem.z > 1.0f) ? 1.0f : 0.0f;
    rst.w = (mem.w > 1.0f) ? 1.0f : 0.0f;
    acc.x += rst.x; acc.y += rst.y; acc.z += rst.z; acc.w += rst.w;
    cur = nxt;

    // t = 63
    mem.x = fmaf(BETA, mem.x, cur.x) - rst.x;
    mem.y = fmaf(BETA, mem.y, cur.y) - rst.y;
    mem.z = fmaf(BETA, mem.z, cur.z) - rst.z;
    mem.w = fmaf(BETA, mem.w, cur.w) - rst.w;
    acc.x += (mem.x > 1.0f) ? 1.0f : 0.0f;
    acc.y += (mem.y > 1.0f) ? 1.0f : 0.0f;
    acc.z += (mem.z > 1.0f) ? 1.0f : 0.0f;
    acc.w += (mem.w > 1.0f) ? 1.0f : 0.0f;

    *(float4*)&out[s * 8 + half * 4] = acc;
}

// ---------------------------------------------------------------------------
extern "C" void kernel_launch(void* const* d_in, const int* in_sizes, int n_in,
                              void* d_out, int out_size)
{
    const float* x  = (const float*)d_in[0];
    const float* W1 = (const float*)d_in[1];
    const float* b1 = (const float*)d_in[2];
    const float* W2 = (const float*)d_in[3];
    const float* b2 = (const float*)d_in[4];
    float* out = (float*)d_out;

    k0_w1t<<<dim3(8, 4), dim3(32, 8)>>>(W1);

    cudaFuncSetAttribute(k1_fc1, cudaFuncAttributeMaxDynamicSharedMemorySize, K1_SMEM);
    k1_fc1<<<BN / 64, 128, K1_SMEM>>>(x, b1);

    k2_lif1<<<BN / 8, 256>>>();

    cudaFuncSetAttribute(k3_lif2, cudaFuncAttributeMaxDynamicSharedMemorySize, 65536);

    // PDL launch of k3 (prologue overlaps k2); plain-launch fallback.
    cudaLaunchConfig_t cfg = {};
    cfg.gridDim       = dim3(NSM * 2);
    cfg.blockDim      = dim3(256);
    cfg.dynamicSmemBytes = 65536;
    cfg.stream        = 0;
    cudaLaunchAttribute attrs[1];
    attrs[0].id = cudaLaunchAttributeProgrammaticStreamSerialization;
    attrs[0].val.programmaticStreamSerializationAllowed = 1;
    cfg.attrs    = attrs;
    cfg.numAttrs = 1;
    cudaError_t e = cudaLaunchKernelEx(&cfg, k3_lif2, W2, b2, (float*)out);
    if (e != cudaSuccess) {
        (void)cudaGetLastError();   // clear
        k3_lif2<<<NSM * 2, 256, 65536>>>(W2, b2, out);
    }
}

// round 16
// speedup vs baseline: 1.0546x; 1.0106x over previous
#include <cuda_runtime.h>
#include <stdint.h>

#define BN      16384
#define IN_DIM  256
#define HID     128
#define NCLS    8
#define T_STEPS 64
#define BETA    0.9f
#define NSM     148

// Scratch (no cudaMalloc allowed)
__device__ float g_cur1[BN * HID];          // 8 MB
__device__ uint4 g_masks[T_STEPS * BN];     // 16 MB  [t][s] spike masks
__device__ float g_W1T[IN_DIM * HID];       // 128 KB W1 transposed: [k][h]

static __device__ __forceinline__ unsigned long long fdup(float v)
{
    unsigned long long r;
    unsigned u = __float_as_uint(v);
    asm("mov.b64 %0, {%1, %1};" : "=l"(r) : "r"(u));
    return r;
}

static __device__ __forceinline__ unsigned long long fpack(float lo, float hi)
{
    unsigned long long r;
    asm("mov.b64 %0, {%1, %2};" : "=l"(r) : "f"(lo), "f"(hi));
    return r;
}

static __device__ __forceinline__ void funpack(unsigned long long v,
                                               float& lo, float& hi)
{
    asm("mov.b64 {%0, %1}, %2;" : "=f"(lo), "=f"(hi) : "l"(v));
}

// ---------------------------------------------------------------------------
// K0: W1T[k][h] = W1[h][k] — tiled transpose (R11/R13 version, ~1 us).
// ---------------------------------------------------------------------------
__global__ void k0_w1t(const float* __restrict__ W1)
{
    __shared__ float t[32][33];
    const int kb = blockIdx.x * 32;
    const int hb = blockIdx.y * 32;
    const int lx = threadIdx.x;
    const int ly = threadIdx.y;
#pragma unroll
    for (int i = 0; i < 4; i++)
        t[ly + i * 8][lx] = W1[(hb + ly + i * 8) * IN_DIM + kb + lx];
    __syncthreads();
#pragma unroll
    for (int i = 0; i < 4; i++)
        g_W1T[(kb + ly + i * 8) * HID + hb + lx] = t[lx][ly + i * 8];
}

// ---------------------------------------------------------------------------
// K1: cur1 = x @ W1^T + b1 — R9's 256-thread SCALAR version (measured best:
// k1+k2 = 54.0 us in R9 vs 58.1 for the FFMA2/128-thread variant).
// CTA 64s x 128h, 256 thr, 8s x 4h per thread, k-ascending fmaf chains.
// ---------------------------------------------------------------------------
#define XS_STRIDE 36

__global__ __launch_bounds__(256) void k1_fc1(const float* __restrict__ x,
                                              const float* __restrict__ b1)
{
    __shared__ float xs[64 * XS_STRIDE];
    __shared__ float ws[32 * HID];

    const int tid = threadIdx.x;
    const int bs  = blockIdx.x * 64;
    const int c   = tid & 7;
    const int r   = tid >> 3;

    const int xf0_s = tid >> 3,         xf0_k = (tid & 7) * 4;
    const int xf1_s = (256 + tid) >> 3, xf1_k = ((256 + tid) & 7) * 4;

    float4 px0, px1, pw[4];

    px0 = *(const float4*)&x[(bs + xf0_s) * IN_DIM + xf0_k];
    px1 = *(const float4*)&x[(bs + xf1_s) * IN_DIM + xf1_k];
#pragma unroll
    for (int i = 0; i < 4; i++) {
        int f  = i * 256 + tid;
        int kk = f >> 5;
        int h4 = (f & 31) * 4;
        pw[i] = *(const float4*)&g_W1T[kk * HID + h4];
    }

    float acc[4][8];
#pragma unroll
    for (int i = 0; i < 4; i++)
#pragma unroll
        for (int j = 0; j < 8; j++) acc[i][j] = 0.0f;

    for (int ch = 0; ch < IN_DIM / 32; ch++) {
        *(float4*)&xs[xf0_s * XS_STRIDE + xf0_k] = px0;
        *(float4*)&xs[xf1_s * XS_STRIDE + xf1_k] = px1;
#pragma unroll
        for (int i = 0; i < 4; i++) {
            int f  = i * 256 + tid;
            int kk = f >> 5;
            int h4 = (f & 31) * 4;
            *(float4*)&ws[kk * HID + h4] = pw[i];
        }
        __syncthreads();

        if (ch + 1 < IN_DIM / 32) {
            int kc = (ch + 1) * 32;
            px0 = *(const float4*)&x[(bs + xf0_s) * IN_DIM + kc + xf0_k];
            px1 = *(const float4*)&x[(bs + xf1_s) * IN_DIM + kc + xf1_k];
#pragma unroll
            for (int i = 0; i < 4; i++) {
                int f  = i * 256 + tid;
                int kk = f >> 5;
                int h4 = (f & 31) * 4;
                pw[i] = *(const float4*)&g_W1T[(kc + kk) * HID + h4];
            }
        }

#pragma unroll
        for (int k = 0; k < 32; k += 4) {
            float4 xv[8];
#pragma unroll
            for (int j = 0; j < 8; j++)
                xv[j] = *(const float4*)&xs[(c + 8 * j) * XS_STRIDE + k];
            float4 wv[4];
#pragma unroll
            for (int kk = 0; kk < 4; kk++)
                wv[kk] = *(const float4*)&ws[(k + kk) * HID + r * 4];
#pragma unroll
            for (int kk = 0; kk < 4; kk++) {
                float w0 = wv[kk].x, w1 = wv[kk].y, w2 = wv[kk].z, w3 = wv[kk].w;
#pragma unroll
                for (int j = 0; j < 8; j++) {
                    float xvk = (kk == 0) ? xv[j].x : (kk == 1) ? xv[j].y
                              : (kk == 2) ? xv[j].z : xv[j].w;
                    acc[0][j] = fmaf(w0, xvk, acc[0][j]);
                    acc[1][j] = fmaf(w1, xvk, acc[1][j]);
                    acc[2][j] = fmaf(w2, xvk, acc[2][j]);
                    acc[3][j] = fmaf(w3, xvk, acc[3][j]);
                }
            }
        }
        __syncthreads();
    }

    float4 b1v = *(const float4*)&b1[r * 4];
#pragma unroll
    for (int j = 0; j < 8; j++) {
        int s = bs + c + 8 * j;
        float4 o;
        o.x = acc[0][j] + b1v.x;
        o.y = acc[1][j] + b1v.y;
        o.z = acc[2][j] + b1v.z;
        o.w = acc[3][j] + b1v.w;
        *(float4*)&g_cur1[s * HID + r * 4] = o;
    }
}

// ---------------------------------------------------------------------------
// K2: layer-1 LIF + ballots, sample pairs in f32x2 (R14 version, bitwise
// identical per lane; measured -2.3 us vs scalar).
// ---------------------------------------------------------------------------
__global__ __launch_bounds__(256) void k2_lif1()
{
    __shared__ uint32_t sm[T_STEPS][8][4];

    const int tid  = threadIdx.x;
    const int w    = tid >> 5;
    const int lane = tid & 31;
    const int g    = w & 3;
    const int q    = w >> 2;
    const int sb   = blockIdx.x * 8 + q * 4;
    const int h    = g * 32 + lane;

    float c0 = g_cur1[(sb + 0) * HID + h];
    float c1 = g_cur1[(sb + 1) * HID + h];
    float c2 = g_cur1[(sb + 2) * HID + h];
    float c3 = g_cur1[(sb + 3) * HID + h];

    const unsigned long long beta2 = fdup(BETA);
    unsigned long long cur01 = fpack(c0, c1);
    unsigned long long cur23 = fpack(c2, c3);
    unsigned long long mem01 = fpack(0.0f, 0.0f);
    unsigned long long mem23 = fpack(0.0f, 0.0f);
    unsigned long long rst01 = fpack(-0.0f, -0.0f);
    unsigned long long rst23 = fpack(-0.0f, -0.0f);

    const unsigned FULL = 0xffffffffu;

#pragma unroll 4
    for (int t = 0; t < T_STEPS; t++) {
        asm("fma.rn.f32x2 %0, %1, %0, %2;" : "+l"(mem01) : "l"(beta2), "l"(cur01));
        asm("fma.rn.f32x2 %0, %1, %0, %2;" : "+l"(mem23) : "l"(beta2), "l"(cur23));
        asm("add.rn.f32x2 %0, %0, %1;" : "+l"(mem01) : "l"(rst01));
        asm("add.rn.f32x2 %0, %0, %1;" : "+l"(mem23) : "l"(rst23));

        float m0, m1, m2, m3;
        funpack(mem01, m0, m1);
        funpack(mem23, m2, m3);

        unsigned b0 = __ballot_sync(FULL, m0 > 1.0f);
        unsigned b1 = __ballot_sync(FULL, m1 > 1.0f);
        unsigned b2 = __ballot_sync(FULL, m2 > 1.0f);
        unsigned b3 = __ballot_sync(FULL, m3 > 1.0f);

        float r0 = (m0 > 1.0f) ? -1.0f : -0.0f;
        float r1 = (m1 > 1.0f) ? -1.0f : -0.0f;
        float r2 = (m2 > 1.0f) ? -1.0f : -0.0f;
        float r3 = (m3 > 1.0f) ? -1.0f : -0.0f;
        rst01 = fpack(r0, r1);
        rst23 = fpack(r2, r3);

        if (lane == 0) {
            sm[t][q * 4 + 0][g] = b0;
            sm[t][q * 4 + 1][g] = b1;
            sm[t][q * 4 + 2][g] = b2;
            sm[t][q * 4 + 3][g] = b3;
        }
    }
    __syncthreads();

    for (int idx = tid; idx < T_STEPS * 8; idx += 256) {
        int t  = idx >> 3;
        int sl = idx & 7;
        g_masks[t * BN + blockIdx.x * 8 + sl] = *(const uint4*)&sm[t][sl][0];
    }
}

// ---------------------------------------------------------------------------
// K3: fused layer-2 LUT + LIF — EXACT R13 version (best measured: 58.1 us).
// Grid 148x2 balanced, 128 thr, 64 KB LUT, depth-2 software pipeline.
// ---------------------------------------------------------------------------
static __device__ __forceinline__ float4 f4add(float4 a, float4 b)
{
    return make_float4(a.x + b.x, a.y + b.y, a.z + b.z, a.w + b.w);
}

static __device__ __forceinline__ float4 lut_tree(const float* __restrict__ lut,
                                                  uint4 m, float4 b2v)
{
    uint32_t w[4] = {m.x, m.y, m.z, m.w};
    float4 sg[4];
#pragma unroll
    for (int g = 0; g < 4; g++) {
        const float* lg = &lut[g * 4096];
        uint32_t wg = w[g];
        float4 q0 = *(const float4*)&lg[            ((wg        & 255u) << 2)];
        float4 q1 = *(const float4*)&lg[1 * 1024 + (((wg >> 8)  & 255u) << 2)];
        float4 q2 = *(const float4*)&lg[2 * 1024 + (((wg >> 16) & 255u) << 2)];
        float4 q3 = *(const float4*)&lg[3 * 1024 + ((wg >> 24)          << 2)];
        sg[g] = f4add(f4add(q0, q1), f4add(q2, q3));
    }
    return f4add(f4add(f4add(sg[0], sg[1]), f4add(sg[2], sg[3])), b2v);
}

__global__ __launch_bounds__(128) void k3_lif2(const float* __restrict__ W2,
                                               const float* __restrict__ b2,
                                               float* __restrict__ out)
{
    extern __shared__ float lut[];   // [16][256] float4
    const int tid  = threadIdx.x;
    const int half = blockIdx.x & 1;
    const int bi   = blockIdx.x >> 1;          // 0..147

    {
        const int chunk = tid >> 3;            // 0..15
        const int bbase = (tid & 7) * 32;
        float w[4][8];
#pragma unroll
        for (int cc = 0; cc < 4; cc++)
#pragma unroll
            for (int j = 0; j < 8; j++)
                w[cc][j] = W2[(half * 4 + cc) * HID + chunk * 8 + j];

        for (int i = 0; i < 32; i++) {
            int byt = bbase + i;
            float4 v = make_float4(0.f, 0.f, 0.f, 0.f);
#pragma unroll
            for (int j = 0; j < 8; j++) {
                if ((byt >> j) & 1) {
                    v.x += w[0][j]; v.y += w[1][j];
                    v.z += w[2][j]; v.w += w[3][j];
                }
            }
            *(float4*)&lut[(chunk * 256 + byt) * 4] = v;
        }
    }
    __syncthreads();

    const int s_begin = (bi * BN) / NSM;
    const int s_end   = ((bi + 1) * BN) / NSM;
    const int s       = s_begin + tid;
    if (s >= s_end) return;

    float4 b2v = make_float4(b2[half * 4 + 0], b2[half * 4 + 1],
                             b2[half * 4 + 2], b2[half * 4 + 3]);

    const uint4* mp = &g_masks[s];

    uint4 mc = mp[2 * BN];                    // mask t = 2
    float4 cur = lut_tree(lut, mp[0],  b2v);  // current t = 0
    float4 nxt = lut_tree(lut, mp[BN], b2v);  // current t = 1

    float4 mem = make_float4(0.f, 0.f, 0.f, 0.f);
    float4 acc = mem, rst = mem;

#pragma unroll 2
    for (int t = 0; t < T_STEPS - 2; t++) {
        int tp = (t + 3 < T_STEPS) ? (t + 3) : (T_STEPS - 1);
        uint4 mnew = mp[(size_t)tp * BN];

        float4 n2 = lut_tree(lut, mc, b2v);
        mc = mnew;

        mem.x = fmaf(BETA, mem.x, cur.x) - rst.x;
        mem.y = fmaf(BETA, mem.y, cur.y) - rst.y;
        mem.z = fmaf(BETA, mem.z, cur.z) - rst.z;
        mem.w = fmaf(BETA, mem.w, cur.w) - rst.w;
        rst.x = (mem.x > 1.0f) ? 1.0f : 0.0f;
        rst.y = (mem.y > 1.0f) ? 1.0f : 0.0f;
        rst.z = (mem.z > 1.0f) ? 1.0f : 0.0f;
        rst.w = (mem.w > 1.0f) ? 1.0f : 0.0f;
        acc.x += rst.x; acc.y += rst.y; acc.z += rst.z; acc.w += rst.w;

        cur = nxt;
        nxt = n2;
    }

    // t = 62
    mem.x = fmaf(BETA, mem.x, cur.x) - rst.x;
    mem.y = fmaf(BETA, mem.y, cur.y) - rst.y;
    mem.z = fmaf(BETA, mem.z, cur.z) - rst.z;
    mem.w = fmaf(BETA, mem.w, cur.w) - rst.w;
    rst.x = (mem.x > 1.0f) ? 1.0f : 0.0f;
    rst.y = (mem.y > 1.0f) ? 1.0f : 0.0f;
    rst.z = (mem.z > 1.0f) ? 1.0f : 0.0f;
    rst.w = (mem.w > 1.0f) ? 1.0f : 0.0f;
    acc.x += rst.x; acc.y += rst.y; acc.z += rst.z; acc.w += rst.w;
    cur = nxt;

    // t = 63
    mem.x = fmaf(BETA, mem.x, cur.x) - rst.x;
    mem.y = fmaf(BETA, mem.y, cur.y) - rst.y;
    mem.z = fmaf(BETA, mem.z, cur.z) - rst.z;
    mem.w = fmaf(BETA, mem.w, cur.w) - rst.w;
    acc.x += (mem.x > 1.0f) ? 1.0f : 0.0f;
    acc.y += (mem.y > 1.0f) ? 1.0f : 0.0f;
    acc.z += (mem.z > 1.0f) ? 1.0f : 0.0f;
    acc.w += (mem.w > 1.0f) ? 1.0f : 0.0f;

    *(float4*)&out[s * 8 + half * 4] = acc;
}

// ---------------------------------------------------------------------------
extern "C" void kernel_launch(void* const* d_in, const int* in_sizes, int n_in,
                              void* d_out, int out_size)
{
    const float* x  = (const float*)d_in[0];
    const float* W1 = (const float*)d_in[1];
    const float* b1 = (const float*)d_in[2];
    const float* W2 = (const float*)d_in[3];
    const float* b2 = (const float*)d_in[4];
    float* out = (float*)d_out;

    k0_w1t<<<dim3(8, 4), dim3(32, 8)>>>(W1);
    k1_fc1<<<BN / 64, 256>>>(x, b1);
    k2_lif1<<<BN / 8, 256>>>();

    cudaFuncSetAttribute(k3_lif2, cudaFuncAttributeMaxDynamicSharedMemorySize, 65536);
    k3_lif2<<<NSM * 2, 128, 65536>>>(W2, b2, out);
}